// round 1
// baseline (speedup 1.0000x reference)
#include <cuda_runtime.h>
#include <math.h>

#define NN 65536
#define NE 1048576
#define NB 512

// ---------------- scratch (static __device__, no allocation) ----------------
__device__ float d_vis[NN * 64];
__device__ float d_x77[NN * 77];
__device__ float d_h1[NN * 256];
__device__ float d_out1[NN * 256];
__device__ float d_as1[NN * 4];
__device__ float d_ad1[NN * 4];
__device__ float d_asum1[NE * 4];
__device__ float d_h2[NN * 64];
__device__ float d_out2[NN * 64];
__device__ float d_as2[NN];
__device__ float d_ad2[NN];
__device__ float d_asum2[NE];
__device__ int   d_deg[NN];
__device__ int   d_off[NN + 1];
__device__ int   d_cur[NN];
__device__ int   d_csr[NE];
__device__ float d_scene[NB * 128];
__device__ float d_gate[NN];
__device__ int   d_bs[NB];
__device__ int   d_be[NB];
__device__ float d_rel[NB * 64];
__device__ float d_we1[20];   // [k][h] k<5, h<4
__device__ float d_we2[5];

// ---------------- helpers ----------------
__device__ __forceinline__ float warpMaxAll(float v) {
    #pragma unroll
    for (int o = 16; o; o >>= 1) v = fmaxf(v, __shfl_xor_sync(0xffffffffu, v, o));
    return v;
}
__device__ __forceinline__ float warpSumAll(float v) {
    #pragma unroll
    for (int o = 16; o; o >>= 1) v += __shfl_xor_sync(0xffffffffu, v, o);
    return v;
}
__device__ __forceinline__ float leaky02(float v) { return v > 0.f ? v : 0.2f * v; }

// ---------------- tiny precompute: We . att_edge per head ----------------
__global__ void compute_we_kernel(const float* __restrict__ g1We, const float* __restrict__ g1ae,
                                  const float* __restrict__ g2We, const float* __restrict__ g2ae) {
    int t = threadIdx.x;
    if (t < 20) {
        int k = t / 4, h = t % 4;
        float s = 0.f;
        for (int c = 0; c < 64; c++) s += g1We[k * 256 + h * 64 + c] * g1ae[h * 64 + c];
        d_we1[k * 4 + h] = s;
    } else if (t < 25) {
        int k = t - 20;
        float s = 0.f;
        for (int c = 0; c < 64; c++) s += g2We[k * 64 + c] * g2ae[c];
        d_we2[k] = s;
    }
}

// ---------------- generic tiled fp32 GEMM: C = act(A[M,K] @ W[K,Nc] + bias) ----------------
template <int BM, int BN, int BK, int TM, int TN, bool RELU, bool BIAS>
__global__ void gemm_kernel(const float* __restrict__ A, const float* __restrict__ W,
                            const float* __restrict__ bias, float* __restrict__ C,
                            int M, int K, int Nc) {
    constexpr int THREADS = (BM / TM) * (BN / TN);
    __shared__ float As[BK][BM + 4];
    __shared__ float Ws[BK][BN];
    int tid = threadIdx.x;
    int tx = tid % (BN / TN);
    int ty = tid / (BN / TN);
    int row0 = blockIdx.y * BM;
    int col0 = blockIdx.x * BN;
    float acc[TM][TN];
    #pragma unroll
    for (int i = 0; i < TM; i++)
        #pragma unroll
        for (int j = 0; j < TN; j++) acc[i][j] = 0.f;

    for (int k0 = 0; k0 < K; k0 += BK) {
        #pragma unroll
        for (int i = tid; i < BM * BK; i += THREADS) {
            int m = i / BK, kk = i % BK;
            float v = 0.f;
            if (k0 + kk < K) v = A[(long)(row0 + m) * K + k0 + kk];
            As[kk][m] = v;
        }
        #pragma unroll
        for (int i = tid; i < BK * BN; i += THREADS) {
            int kk = i / BN, nn = i % BN;
            float v = 0.f;
            if (k0 + kk < K) v = W[(long)(k0 + kk) * Nc + col0 + nn];
            Ws[kk][nn] = v;
        }
        __syncthreads();
        #pragma unroll
        for (int kk = 0; kk < BK; kk++) {
            float a[TM], b[TN];
            #pragma unroll
            for (int i = 0; i < TM; i++) a[i] = As[kk][ty * TM + i];
            #pragma unroll
            for (int j = 0; j < TN; j++) b[j] = Ws[kk][tx * TN + j];
            #pragma unroll
            for (int i = 0; i < TM; i++)
                #pragma unroll
                for (int j = 0; j < TN; j++) acc[i][j] = fmaf(a[i], b[j], acc[i][j]);
        }
        __syncthreads();
    }
    #pragma unroll
    for (int i = 0; i < TM; i++) {
        #pragma unroll
        for (int j = 0; j < TN; j++) {
            float v = acc[i][j];
            int col = col0 + tx * TN + j;
            if (BIAS) v += bias[col];
            if (RELU) v = fmaxf(v, 0.f);
            C[(long)(row0 + ty * TM + i) * Nc + col] = v;
        }
    }
}

// ---------------- concat [x(13) | vis(64)] -> x77 ----------------
__global__ void concat_kernel(const float* __restrict__ x) {
    int idx = blockIdx.x * blockDim.x + threadIdx.x;
    if (idx >= NN * 77) return;
    int n = idx / 77, k = idx - n * 77;
    d_x77[idx] = (k < 13) ? x[n * 13 + k] : d_vis[n * 64 + (k - 13)];
}

// ---------------- per-node attention dots (H=4, width 256) ----------------
__global__ void as_ad_h4_kernel(const float* __restrict__ asrc, const float* __restrict__ adst) {
    int w = (blockIdx.x * blockDim.x + threadIdx.x) >> 5;
    if (w >= NN) return;
    int lane = threadIdx.x & 31;
    int gc = lane * 8;
    const float4* hp = (const float4*)(d_h1 + (long)w * 256 + gc);
    float4 p0 = hp[0], p1 = hp[1];
    const float4* sp = (const float4*)(asrc + gc);
    float4 s0 = sp[0], s1 = sp[1];
    const float4* dp = (const float4*)(adst + gc);
    float4 q0 = dp[0], q1 = dp[1];
    float ps = p0.x * s0.x + p0.y * s0.y + p0.z * s0.z + p0.w * s0.w +
               p1.x * s1.x + p1.y * s1.y + p1.z * s1.z + p1.w * s1.w;
    float pd = p0.x * q0.x + p0.y * q0.y + p0.z * q0.z + p0.w * q0.w +
               p1.x * q1.x + p1.y * q1.y + p1.z * q1.z + p1.w * q1.w;
    #pragma unroll
    for (int o = 4; o; o >>= 1) {
        ps += __shfl_xor_sync(0xffffffffu, ps, o);
        pd += __shfl_xor_sync(0xffffffffu, pd, o);
    }
    if ((lane & 7) == 0) {
        int h = lane >> 3;
        d_as1[w * 4 + h] = ps;
        d_ad1[w * 4 + h] = pd;
    }
}

// ---------------- per-node attention dots (H=1, width 64) ----------------
__global__ void as_ad_h1_kernel(const float* __restrict__ asrc, const float* __restrict__ adst) {
    int w = (blockIdx.x * blockDim.x + threadIdx.x) >> 5;
    if (w >= NN) return;
    int lane = threadIdx.x & 31;
    int gc = lane * 2;
    float2 p = *(const float2*)(d_h2 + (long)w * 64 + gc);
    float2 s = *(const float2*)(asrc + gc);
    float2 q = *(const float2*)(adst + gc);
    float ps = p.x * s.x + p.y * s.y;
    float pd = p.x * q.x + p.y * q.y;
    ps = warpSumAll(ps);
    pd = warpSumAll(pd);
    if (lane == 0) { d_as2[w] = ps; d_ad2[w] = pd; }
}

// ---------------- CSR build ----------------
__global__ void init_kernel() {
    int i = blockIdx.x * blockDim.x + threadIdx.x;
    if (i < NN) d_deg[i] = 0;
    if (i < NB) { d_bs[i] = NN; d_be[i] = 0; }
}
__global__ void hist_kernel(const int* __restrict__ dst) {
    int e = blockIdx.x * blockDim.x + threadIdx.x;
    if (e < NE) atomicAdd(&d_deg[dst[e]], 1);
}
__global__ void scan_kernel() {
    __shared__ int sh[1024];
    int t = threadIdx.x;
    int base = t * (NN / 1024);
    int tot = 0;
    for (int i = 0; i < NN / 1024; i++) tot += d_deg[base + i];
    sh[t] = tot;
    __syncthreads();
    for (int o = 1; o < 1024; o <<= 1) {
        int v = (t >= o) ? sh[t - o] : 0;
        __syncthreads();
        sh[t] += v;
        __syncthreads();
    }
    int run = sh[t] - tot;
    for (int i = 0; i < NN / 1024; i++) {
        int dg = d_deg[base + i];
        d_off[base + i] = run;
        d_cur[base + i] = run;
        run += dg;
    }
    if (t == 1023) d_off[NN] = run;
}
__global__ void scatter_kernel(const int* __restrict__ dst) {
    int e = blockIdx.x * blockDim.x + threadIdx.x;
    if (e >= NE) return;
    int p = atomicAdd(&d_cur[dst[e]], 1);
    d_csr[p] = e;
}

// ---------------- per-edge partial logits ----------------
__global__ void asum1_kernel(const int* __restrict__ src, const float* __restrict__ ea) {
    int e = blockIdx.x * blockDim.x + threadIdx.x;
    if (e >= NE) return;
    float a[5];
    #pragma unroll
    for (int k = 0; k < 5; k++) a[k] = ea[e * 5 + k];
    int s = src[e];
    float4 as4 = *(const float4*)(d_as1 + s * 4);
    float v0 = as4.x, v1 = as4.y, v2 = as4.z, v3 = as4.w;
    #pragma unroll
    for (int k = 0; k < 5; k++) {
        v0 = fmaf(a[k], d_we1[k * 4 + 0], v0);
        v1 = fmaf(a[k], d_we1[k * 4 + 1], v1);
        v2 = fmaf(a[k], d_we1[k * 4 + 2], v2);
        v3 = fmaf(a[k], d_we1[k * 4 + 3], v3);
    }
    *(float4*)(d_asum1 + (long)e * 4) = make_float4(v0, v1, v2, v3);
}
__global__ void asum2_kernel(const int* __restrict__ src, const float* __restrict__ ea) {
    int e = blockIdx.x * blockDim.x + threadIdx.x;
    if (e >= NE) return;
    float v = d_as2[src[e]];
    #pragma unroll
    for (int k = 0; k < 5; k++) v = fmaf(ea[e * 5 + k], d_we2[k], v);
    d_asum2[e] = v;
}

// ---------------- GAT1 aggregate (warp per node, 4 heads x 64 ch) ----------------
__global__ void gat1_agg_kernel(const int* __restrict__ src, const float* __restrict__ bias) {
    int n = (blockIdx.x * blockDim.x + threadIdx.x) >> 5;
    if (n >= NN) return;
    int lane = threadIdx.x & 31;
    int beg = d_off[n], end = d_off[n + 1];
    float4 ad4 = *(const float4*)(d_ad1 + n * 4);
    float ad[4] = {ad4.x, ad4.y, ad4.z, ad4.w};
    float mx[4] = {-INFINITY, -INFINITY, -INFINITY, -INFINITY};
    for (int i = beg + lane; i < end; i += 32) {
        int e = d_csr[i];
        float4 a = *(const float4*)(d_asum1 + (long)e * 4);
        mx[0] = fmaxf(mx[0], leaky02(a.x + ad[0]));
        mx[1] = fmaxf(mx[1], leaky02(a.y + ad[1]));
        mx[2] = fmaxf(mx[2], leaky02(a.z + ad[2]));
        mx[3] = fmaxf(mx[3], leaky02(a.w + ad[3]));
    }
    #pragma unroll
    for (int h = 0; h < 4; h++) mx[h] = warpMaxAll(mx[h]);
    float sm[4] = {0.f, 0.f, 0.f, 0.f};
    for (int i = beg + lane; i < end; i += 32) {
        int e = d_csr[i];
        float4 a = *(const float4*)(d_asum1 + (long)e * 4);
        sm[0] += __expf(leaky02(a.x + ad[0]) - mx[0]);
        sm[1] += __expf(leaky02(a.y + ad[1]) - mx[1]);
        sm[2] += __expf(leaky02(a.z + ad[2]) - mx[2]);
        sm[3] += __expf(leaky02(a.w + ad[3]) - mx[3]);
    }
    float inv[4];
    #pragma unroll
    for (int h = 0; h < 4; h++) {
        sm[h] = warpSumAll(sm[h]);
        inv[h] = 1.f / (sm[h] + 1e-16f);
    }
    int h = lane >> 3;
    int gc = lane * 8;
    float acc[8] = {0.f, 0.f, 0.f, 0.f, 0.f, 0.f, 0.f, 0.f};
    for (int i = beg; i < end; i++) {
        int e = d_csr[i];
        int s = src[e];
        float v = leaky02(d_asum1[(long)e * 4 + h] + ad[h]);
        float w = __expf(v - mx[h]) * inv[h];
        const float4* hp = (const float4*)(d_h1 + (long)s * 256 + gc);
        float4 p0 = hp[0], p1 = hp[1];
        acc[0] = fmaf(p0.x, w, acc[0]); acc[1] = fmaf(p0.y, w, acc[1]);
        acc[2] = fmaf(p0.z, w, acc[2]); acc[3] = fmaf(p0.w, w, acc[3]);
        acc[4] = fmaf(p1.x, w, acc[4]); acc[5] = fmaf(p1.y, w, acc[5]);
        acc[6] = fmaf(p1.z, w, acc[6]); acc[7] = fmaf(p1.w, w, acc[7]);
    }
    float* op = d_out1 + (long)n * 256 + gc;
    #pragma unroll
    for (int j = 0; j < 8; j++) op[j] = fmaxf(acc[j] + bias[gc + j], 0.f);
}

// ---------------- GAT2 aggregate (warp per node, 1 head x 64 ch) ----------------
__global__ void gat2_agg_kernel(const int* __restrict__ src, const float* __restrict__ bias) {
    int n = (blockIdx.x * blockDim.x + threadIdx.x) >> 5;
    if (n >= NN) return;
    int lane = threadIdx.x & 31;
    int beg = d_off[n], end = d_off[n + 1];
    float ad = d_ad2[n];
    float mx = -INFINITY;
    for (int i = beg + lane; i < end; i += 32)
        mx = fmaxf(mx, leaky02(d_asum2[d_csr[i]] + ad));
    mx = warpMaxAll(mx);
    float sm = 0.f;
    for (int i = beg + lane; i < end; i += 32)
        sm += __expf(leaky02(d_asum2[d_csr[i]] + ad) - mx);
    sm = warpSumAll(sm);
    float inv = 1.f / (sm + 1e-16f);
    int gc = lane * 2;
    float a0 = 0.f, a1 = 0.f;
    for (int i = beg; i < end; i++) {
        int e = d_csr[i];
        int s = src[e];
        float v = leaky02(d_asum2[e] + ad);
        float w = __expf(v - mx) * inv;
        float2 p = *(const float2*)(d_h2 + (long)s * 64 + gc);
        a0 = fmaf(p.x, w, a0);
        a1 = fmaf(p.y, w, a1);
    }
    d_out2[(long)n * 64 + gc] = a0 + bias[gc];
    d_out2[(long)n * 64 + gc + 1] = a1 + bias[gc + 1];
}

// ---------------- pooling ----------------
__global__ void gate_kernel(const float* __restrict__ gW, const float* __restrict__ gb) {
    int n = (blockIdx.x * blockDim.x + threadIdx.x) >> 5;
    if (n >= NN) return;
    int lane = threadIdx.x & 31;
    int gc = lane * 2;
    float2 p = *(const float2*)(d_out2 + (long)n * 64 + gc);
    float v = p.x * gW[gc] + p.y * gW[gc + 1];
    v = warpSumAll(v);
    if (lane == 0) d_gate[n] = v + gb[0];
}
__global__ void bbounds_kernel(const int* __restrict__ bv) {
    int n = blockIdx.x * blockDim.x + threadIdx.x;
    if (n >= NN) return;
    int b = bv[n];
    atomicMin(&d_bs[b], n);
    atomicMax(&d_be[b], n + 1);
}
__global__ void pool_kernel() {
    int b = blockIdx.x;
    int s = d_bs[b], e = d_be[b];
    __shared__ float sh[256];
    int t = threadIdx.x;
    if (e <= s) {
        if (t < 64) d_rel[b * 64 + t] = 0.f;
        return;
    }
    float m = -INFINITY;
    for (int n = s + t; n < e; n += 256) m = fmaxf(m, d_gate[n]);
    sh[t] = m;
    __syncthreads();
    for (int o = 128; o; o >>= 1) { if (t < o) sh[t] = fmaxf(sh[t], sh[t + o]); __syncthreads(); }
    m = sh[0];
    __syncthreads();
    float sum = 0.f;
    for (int n = s + t; n < e; n += 256) sum += __expf(d_gate[n] - m);
    sh[t] = sum;
    __syncthreads();
    for (int o = 128; o; o >>= 1) { if (t < o) sh[t] += sh[t + o]; __syncthreads(); }
    float inv = 1.f / (sh[0] + 1e-16f);
    __syncthreads();
    int g = t >> 6, c = t & 63;
    float acc = 0.f;
    for (int n = s + g; n < e; n += 4) {
        float w = __expf(d_gate[n] - m) * inv;
        acc = fmaf(w, d_out2[(long)n * 64 + c], acc);
    }
    sh[t] = acc;
    __syncthreads();
    if (g == 0) d_rel[b * 64 + c] = sh[c] + sh[c + 64] + sh[c + 128] + sh[c + 192];
}

// ---------------- classifier ----------------
__global__ void cls_kernel(const float* __restrict__ w1, const float* __restrict__ b1,
                           const float* __restrict__ w2, const float* __restrict__ b2,
                           float* __restrict__ out) {
    int b = blockIdx.x;
    int t = threadIdx.x;  // 64 threads
    __shared__ float comb[192];
    __shared__ float hid[64];
    for (int k = t; k < 192; k += 64)
        comb[k] = (k < 128) ? d_scene[b * 128 + k] : d_rel[b * 64 + (k - 128)];
    __syncthreads();
    float a = b1[t];
    #pragma unroll 4
    for (int k = 0; k < 192; k++) a = fmaf(comb[k], w1[k * 64 + t], a);
    hid[t] = fmaxf(a, 0.f);
    __syncthreads();
    if (t < 3) {
        float o = b2[t];
        #pragma unroll
        for (int k = 0; k < 64; k++) o = fmaf(hid[k], w2[k * 3 + t], o);
        out[b * 3 + t] = o;
    }
}

// ---------------- launch ----------------
extern "C" void kernel_launch(void* const* d_in, const int* in_sizes, int n_in,
                              void* d_out, int out_size) {
    const float* global_feat = (const float*)d_in[0];
    const float* x           = (const float*)d_in[1];
    const float* roi_feats   = (const float*)d_in[2];
    const int*   edge_index  = (const int*)d_in[3];
    const float* edge_attr   = (const float*)d_in[4];
    const int*   batch_vec   = (const int*)d_in[5];
    const float* roi_W   = (const float*)d_in[6];
    const float* roi_b   = (const float*)d_in[7];
    const float* scene_W = (const float*)d_in[8];
    const float* scene_b = (const float*)d_in[9];
    const float* g1_W   = (const float*)d_in[10];
    const float* g1_as  = (const float*)d_in[11];
    const float* g1_ad  = (const float*)d_in[12];
    const float* g1_We  = (const float*)d_in[13];
    const float* g1_ae  = (const float*)d_in[14];
    const float* g1_b   = (const float*)d_in[15];
    const float* g2_W   = (const float*)d_in[16];
    const float* g2_as  = (const float*)d_in[17];
    const float* g2_ad  = (const float*)d_in[18];
    const float* g2_We  = (const float*)d_in[19];
    const float* g2_ae  = (const float*)d_in[20];
    const float* g2_b   = (const float*)d_in[21];
    const float* gate_W = (const float*)d_in[22];
    const float* gate_b = (const float*)d_in[23];
    const float* cls1_W = (const float*)d_in[24];
    const float* cls1_b = (const float*)d_in[25];
    const float* cls2_W = (const float*)d_in[26];
    const float* cls2_b = (const float*)d_in[27];
    float* out = (float*)d_out;

    const int* src = edge_index;       // row 0
    const int* dst = edge_index + NE;  // row 1

    // device pointers to __device__ globals (resolved at compile time in kernels)
    compute_we_kernel<<<1, 32>>>(g1_We, g1_ae, g2_We, g2_ae);

    // scene = global_feat @ scene_W + b   (512,512)->(512,128)
    {
        float* dscene;
        cudaGetSymbolAddress((void**)&dscene, d_scene);
        gemm_kernel<64, 64, 16, 4, 4, false, true><<<dim3(2, 8), 256>>>(
            global_feat, scene_W, scene_b, dscene, NB, 512, 128);
    }
    // vis = relu(roi_feats @ roi_W + b)   (N,256)->(N,64)
    {
        float* dvis;
        cudaGetSymbolAddress((void**)&dvis, d_vis);
        gemm_kernel<64, 64, 16, 4, 4, true, true><<<dim3(1, NN / 64), 256>>>(
            roi_feats, roi_W, roi_b, dvis, NN, 256, 64);
    }
    concat_kernel<<<(NN * 77 + 255) / 256, 256>>>(x);
    // h1 = x77 @ g1_W   (N,77)->(N,256)
    {
        float *dx77, *dh1;
        cudaGetSymbolAddress((void**)&dx77, d_x77);
        cudaGetSymbolAddress((void**)&dh1, d_h1);
        gemm_kernel<64, 64, 16, 4, 4, false, false><<<dim3(4, NN / 64), 256>>>(
            dx77, g1_W, nullptr, dh1, NN, 77, 256);
    }
    as_ad_h4_kernel<<<NN / 8, 256>>>(g1_as, g1_ad);

    // CSR build (shared by both GAT layers)
    init_kernel<<<NN / 256, 256>>>();
    hist_kernel<<<NE / 256, 256>>>(dst);
    scan_kernel<<<1, 1024>>>();
    scatter_kernel<<<NE / 256, 256>>>(dst);

    asum1_kernel<<<NE / 256, 256>>>(src, edge_attr);
    gat1_agg_kernel<<<NN / 8, 256>>>(src, g1_b);

    // h2 = out1 @ g2_W   (N,256)->(N,64)
    {
        float *dout1, *dh2;
        cudaGetSymbolAddress((void**)&dout1, d_out1);
        cudaGetSymbolAddress((void**)&dh2, d_h2);
        gemm_kernel<64, 64, 16, 4, 4, false, false><<<dim3(1, NN / 64), 256>>>(
            dout1, g2_W, nullptr, dh2, NN, 256, 64);
    }
    as_ad_h1_kernel<<<NN / 8, 256>>>(g2_as, g2_ad);
    asum2_kernel<<<NE / 256, 256>>>(src, edge_attr);
    gat2_agg_kernel<<<NN / 8, 256>>>(src, g2_b);

    // pooling
    gate_kernel<<<NN / 8, 256>>>(gate_W, gate_b);
    bbounds_kernel<<<NN / 256, 256>>>(batch_vec);
    pool_kernel<<<NB, 256>>>();

    // classifier
    cls_kernel<<<NB, 64>>>(cls1_W, cls1_b, cls2_W, cls2_b, out);
}